// round 16
// baseline (speedup 1.0000x reference)
#include <cuda_runtime.h>
#include <cuda_bf16.h>

// NormalsRenderer: B=512, N=512.
// out[b] = normalize( sum_i acc_i * n_i ),  acc_i = sum_{j!=i} exp(-acos(clip(<n_i,n_j>)))
// Identities (uniform positive scales cancel under the final normalize):
//   - division by max(new_weights) dropped; exp(-acos d) = const * exp(asin d)
//   - u = sat(1-|d|);  asin(|d|)*log2e = LHPI + sqrt(u)*Q(u)  (cubic Q)
//   - w = exp2( copysign( LHPI + sqrt(u)*Q(u), d ) )
// 512 rows = 16 groups of 32; 136 unordered group-tiles covered exactly once by 40
// chunks (<=4 i-groups x 1 j-group) over 16 warps/batch = 4 CTAs x 4 warps
// (grid 2048, R12's proven table). Broadcast-j loop: smem holds pre-duplicated
// packed pairs sdx[k]=(x_k,x_k); step s reads j-row gj*32+s via 3 broadcast LDS.64.
// HYBRID eval (new): dot products in fma.rn.f32x2 (operands naturally paired:
// j from LDS.64, i packed once per chunk), EVERYTHING after one d2-unpack is
// scalar — removes all per-step pack sites (the measured ~20-MOV/step marshaling
// tax of the fully-packed eval). Scalar math is bit-identical to the f32x2 lanes.
// Columns: scalar tot -> 9-padded per-warp scratch (1 STS.32/step), conflict-free
// transposed reduce every 8 steps. Diag chunk: diag group LAST; excluded from
// columns via fmaf(last,cmask); self term subtracted bitwise at flush.
// __launch_bounds__(128,9); per-warp smem row accumulators; 4-way atomic merge.

#define NPTS 512
#define TPB  128

typedef unsigned long long ull;
typedef unsigned int uint;

// -log2(e) * p_AS(1-u) re-expanded in u, and log2(e)*pi/2
#define Q0f (-2.0401824f)
#define Q1f (-0.17280645f)
#define Q2f (-0.026074023f)
#define Q3f (-0.027020667f)
#define LHPIf (2.2661800709f)

__device__ float g_stage[2048][3];
__device__ int   g_cnt[512];

// R12's proven 16-warp chunk tables: warp W (0..15) runs up to 3 chunks
// (gj, gib, ng); ng=0 sentinel. Exact cover of all 136 (i<=j) group-tiles;
// diag iff gib+ng-1 == gj (diag group always last in its run).
__constant__ signed char c_gj[16][3] = {
    {3,15,-1},{4,15,-1},{5,15,-1},{6,14,-1},{7,14,-1},{8,13,-1},{9,13,-1},{10,12,-1},
    {11,12,4},{12,11,8},{13,11,12},{14,10,0},{15,2,1},{7,6,5},{8,10,9},{9,14,13}};
__constant__ signed char c_gib[16][3] = {
    {0,0,0},{1,4,0},{2,8,0},{3,3,0},{4,7,0},{5,2,0},{6,6,0},{7,1,0},
    {8,5,0},{9,0,0},{10,4,0},{11,3,0},{12,0,0},{0,0,0},{1,0,0},{2,0,0}};
__constant__ signed char c_ng[16][3] = {
    {4,4,0},{4,4,0},{4,4,0},{4,4,0},{4,4,0},{4,4,0},{4,4,0},{4,4,0},
    {4,4,1},{4,4,1},{4,4,1},{4,4,1},{4,3,2},{4,3,2},{4,3,2},{4,3,2}};

__device__ __forceinline__ ull pack2(float lo, float hi) {
    ull r; asm("mov.b64 %0, {%1, %2};" : "=l"(r) : "f"(lo), "f"(hi)); return r;
}
__device__ __forceinline__ void unpack2(ull v, float& lo, float& hi) {
    asm("mov.b64 {%0, %1}, %2;" : "=f"(lo), "=f"(hi) : "l"(v));
}
__device__ __forceinline__ ull fma2(ull a, ull b, ull c) {
    ull d; asm("fma.rn.f32x2 %0, %1, %2, %3;" : "=l"(d) : "l"(a), "l"(b), "l"(c)); return d;
}
__device__ __forceinline__ ull mul2(ull a, ull b) {
    ull d; asm("mul.rn.f32x2 %0, %1, %2;" : "=l"(d) : "l"(a), "l"(b)); return d;
}
__device__ __forceinline__ float sqrta(float x) {
    float r; asm("sqrt.approx.f32 %0, %1;" : "=f"(r) : "f"(x)); return r;
}
__device__ __forceinline__ float ex2a(float x) {
    float r; asm("ex2.approx.f32 %0, %1;" : "=f"(r) : "f"(x)); return r;
}

// Scalar tail of the weight eval, fed by a dot product d (packed or scalar —
// both produce identical fma.rn rounding).
__device__ __forceinline__ float wfromd(float d) {
    float u = __saturatef(1.0f - fabsf(d));   // FADD.SAT with |.| modifier
    float s = sqrta(u);
    float p = fmaf(u, Q3f, Q2f);
    p = fmaf(u, p, Q1f);
    p = fmaf(u, p, Q0f);
    float g = fmaf(s, p, LHPIf);
    uint  e = __float_as_uint(g) | (__float_as_uint(d) & 0x80000000u);  // 1 LOP3
    return ex2a(__uint_as_float(e));
}

__device__ __forceinline__ float eval1(float xi, float yi, float zi,
                                       float jx, float jy, float jz)
{
    float d = fmaf(zi, jz, fmaf(yi, jy, xi * jx));
    return wfromd(d);
}

// NP packed group-pairs + optional scalar tail group. NG = 2*NP + HS.
// Diag group is always LAST in the run.
template<int NP, bool HS>
__device__ __forceinline__ void process_chunk(const ull* __restrict__ sdx,
                                              const ull* __restrict__ sdy,
                                              const ull* __restrict__ sdz,
                                              float* __restrict__ raw,
                                              float* __restrict__ scratch,  // 288 floats, this warp
                                              int gj, int gib, bool diag, int lane)
{
    constexpr int NG  = 2 * NP + (HS ? 1 : 0);
    constexpr int NPA = (NP > 0) ? NP : 1;

    const float* fsx = (const float*)sdx;   // fsx[2*r] = x_r (lo half of the dup pair)
    const float* fsy = (const float*)sdy;
    const float* fsz = (const float*)sdz;

    // i-side: packed per group-pair (marshaled ONCE per chunk, amortized over 32 steps)
    ull xi[NPA], yi[NPA], zi[NPA];
    #pragma unroll
    for (int p = 0; p < NP; ++p) {
        const int rA = (gib + 2 * p) * 32 + lane;
        const int rB = rA + 32;
        xi[p] = pack2(fsx[2 * rA], fsx[2 * rB]);
        yi[p] = pack2(fsy[2 * rA], fsy[2 * rB]);
        zi[p] = pack2(fsz[2 * rA], fsz[2 * rB]);
    }
    float xs = 0.0f, ys = 0.0f, zs = 0.0f;
    if (HS) {
        const int r = (gib + 2 * NP) * 32 + lane;
        xs = fsx[2 * r]; ys = fsy[2 * r]; zs = fsz[2 * r];
    }

    float ra[NG];
    #pragma unroll
    for (int g = 0; g < NG; ++g) ra[g] = 0.0f;

    const int jbase = gj * 32;
    const float cmask = diag ? 0.0f : 1.0f;   // last group excluded from columns if diag
    const int q  = lane >> 2;                 // flush: this lane reduces column q
    const int rb = (lane & 3) * 8;            // over scratch rows rb..rb+7

    #pragma unroll 1
    for (int bq = 0; bq < 4; ++bq) {
        #pragma unroll
        for (int sq = 0; sq < 8; ++sq) {
            const int s = bq * 8 + sq;
            const ull jx2 = sdx[jbase + s];   // broadcast LDS.64, pre-packed (j,j)
            const ull jy2 = sdy[jbase + s];
            const ull jz2 = sdz[jbase + s];

            float w[NG];
            #pragma unroll
            for (int p = 0; p < NP; ++p) {    // packed dot, then all-scalar tail
                ull dp = fma2(zi[p], jz2, fma2(yi[p], jy2, mul2(xi[p], jx2)));
                float dl, dh; unpack2(dp, dl, dh);
                w[2 * p]     = wfromd(dl);
                w[2 * p + 1] = wfromd(dh);
            }
            if (HS) {
                float jxs, jys, jzs, t_;
                unpack2(jx2, jxs, t_); unpack2(jy2, jys, t_); unpack2(jz2, jzs, t_);
                w[NG - 1] = eval1(xs, ys, zs, jxs, jys, jzs);
            }
            #pragma unroll
            for (int g = 0; g < NG; ++g) ra[g] += w[g];

            float rest = 0.0f;
            #pragma unroll
            for (int g = 0; g < NG - 1; ++g) rest += w[g];
            scratch[lane * 9 + sq] = fmaf(w[NG - 1], cmask, rest);   // fire-and-forget
        }
        __syncwarp();
        // transposed conflict-free reduce of 8 columns (x9 pad => distinct banks)
        float sum = ((scratch[(rb + 0) * 9 + q] + scratch[(rb + 1) * 9 + q])
                   + (scratch[(rb + 2) * 9 + q] + scratch[(rb + 3) * 9 + q]))
                  + ((scratch[(rb + 4) * 9 + q] + scratch[(rb + 5) * 9 + q])
                   + (scratch[(rb + 6) * 9 + q] + scratch[(rb + 7) * 9 + q]));
        sum += __shfl_xor_sync(0xffffffffu, sum, 1);
        sum += __shfl_xor_sync(0xffffffffu, sum, 2);
        if ((lane & 3) == 0) raw[jbase + bq * 8 + q] += sum;
        __syncwarp();
    }

    // Diag correction: self pair went through wfromd identically -> exact cancel.
    float selfw = 0.0f;
    if (diag) {
        const int r = (gib + NG - 1) * 32 + lane;
        selfw = eval1(fsx[2 * r], fsy[2 * r], fsz[2 * r],
                      fsx[2 * r], fsy[2 * r], fsz[2 * r]);
    }

    #pragma unroll
    for (int g = 0; g < NG; ++g) {
        float v = ra[g];
        if (g == NG - 1) v -= selfw;
        raw[(gib + g) * 32 + lane] += v;
    }
}

__global__ __launch_bounds__(TPB, 9)
void normals_hybrid_kernel(const float* __restrict__ normals,
                           float* __restrict__ out)
{
    __shared__ ull   sdx[NPTS], sdy[NPTS], sdz[NPTS];   // 12 KB duplicated pairs
    __shared__ float rowaccW[4][NPTS];                  // 8 KB per-warp row acc
    __shared__ float colscratch[4][288];                // 4.5 KB per-warp (9-padded)
    __shared__ float sred[3][4];

    const int b  = blockIdx.x >> 2;       // batch
    const int qr = blockIdx.x & 3;        // quarter within batch
    const int t    = threadIdx.x;
    const int lane = t & 31;
    const int wl   = t >> 5;

    const float* base = normals + (size_t)b * NPTS * 3;
    #pragma unroll
    for (int r = t; r < NPTS; r += TPB) {
        float x = base[r * 3 + 0], y = base[r * 3 + 1], z = base[r * 3 + 2];
        sdx[r] = pack2(x, x); sdy[r] = pack2(y, y); sdz[r] = pack2(z, z);
    }
    #pragma unroll
    for (int idx = t; idx < 4 * NPTS; idx += TPB)
        ((float*)rowaccW)[idx] = 0.0f;
    __syncthreads();

    const int W = qr * 4 + wl;            // global warp id 0..15
    float* raw = rowaccW[wl];
    float* scr = colscratch[wl];

    #pragma unroll 1
    for (int c = 0; c < 3; ++c) {
        const int ng = c_ng[W][c];
        if (ng == 0) break;
        const int gj  = c_gj[W][c];
        const int gib = c_gib[W][c];
        const bool dg = (gib + ng - 1 == gj);
        switch (ng) {
            case 4: process_chunk<2, false>(sdx, sdy, sdz, raw, scr, gj, gib, dg, lane); break;
            case 3: process_chunk<1, true >(sdx, sdy, sdz, raw, scr, gj, gib, dg, lane); break;
            case 2: process_chunk<1, false>(sdx, sdy, sdz, raw, scr, gj, gib, dg, lane); break;
            default: process_chunk<0, true >(sdx, sdy, sdz, raw, scr, gj, gib, dg, lane); break;
        }
    }
    __syncthreads();

    // weighted sum over rows handled by this thread
    float vx = 0.0f, vy = 0.0f, vz = 0.0f;
    #pragma unroll
    for (int r = t; r < NPTS; r += TPB) {
        float wsum = (rowaccW[0][r] + rowaccW[1][r])
                   + (rowaccW[2][r] + rowaccW[3][r]);
        float nx = ((const float*)sdx)[2 * r];
        float ny = ((const float*)sdy)[2 * r];
        float nz = ((const float*)sdz)[2 * r];
        vx = fmaf(wsum, nx, vx);
        vy = fmaf(wsum, ny, vy);
        vz = fmaf(wsum, nz, vz);
    }

    #pragma unroll
    for (int s = 16; s >= 1; s >>= 1) {
        vx += __shfl_down_sync(0xffffffffu, vx, s);
        vy += __shfl_down_sync(0xffffffffu, vy, s);
        vz += __shfl_down_sync(0xffffffffu, vz, s);
    }
    if (lane == 0) { sred[0][wl] = vx; sred[1][wl] = vy; sred[2][wl] = vz; }
    __syncthreads();

    if (t == 0) {
        float rx = (sred[0][0] + sred[0][1]) + (sred[0][2] + sred[0][3]);
        float ry = (sred[1][0] + sred[1][1]) + (sred[1][2] + sred[1][3]);
        float rz = (sred[2][0] + sred[2][1]) + (sred[2][2] + sred[2][3]);
        g_stage[blockIdx.x][0] = rx;
        g_stage[blockIdx.x][1] = ry;
        g_stage[blockIdx.x][2] = rz;
        __threadfence();
        int old = atomicAdd(&g_cnt[b], 1);
        if (old == 3) {   // 4th arrival: combine all quarters + normalize + write
            __threadfence();
            const int baseIdx = b * 4;
            rx = 0.0f; ry = 0.0f; rz = 0.0f;
            #pragma unroll
            for (int k = 0; k < 4; ++k) {
                rx += g_stage[baseIdx + k][0];
                ry += g_stage[baseIdx + k][1];
                rz += g_stage[baseIdx + k][2];
            }
            float ss  = fmaf(rx, rx, fmaf(ry, ry, rz * rz));
            float inv = rsqrtf(fmaxf(ss, 1e-20f));
            out[b * 3 + 0] = rx * inv;
            out[b * 3 + 1] = ry * inv;
            out[b * 3 + 2] = rz * inv;
            g_cnt[b] = 0;   // deterministic state for graph replay
        }
    }
}

extern "C" void kernel_launch(void* const* d_in, const int* in_sizes, int n_in,
                              void* d_out, int out_size)
{
    const float* normals = (const float*)d_in[0];  // [512, 512, 3] f32
    // d_in[1] = weights: unused by the reference math.
    float* out = (float*)d_out;                    // [512, 3] f32

    normals_hybrid_kernel<<<2048, TPB>>>(normals, out);
}